// round 5
// baseline (speedup 1.0000x reference)
#include <cuda_runtime.h>

#define BATCH   8192
#define CLASSES 10000
#define C4      2500          // float4 per row
#define THREADS 512
#define GRID    304           // 2 persistent CTAs per SM (152 SMs on GB300)

__device__ float g_part[GRID][CLASSES];   // per-CTA partials (fully overwritten)
__device__ float g_counts[CLASSES];

// ---------------------------------------------------------------- zero counts + out
__global__ void k_zero(float* __restrict__ out) {
    int i = blockIdx.x * blockDim.x + threadIdx.x;
    if (i < CLASSES) g_counts[i] = 0.0f;
    if (i == 0) out[0] = 0.0f;
}

// ---------------------------------------------------------------- persistent main
// Each CTA: 40KB fp32 per-class accumulator in SMEM. Per row: coalesced float4
// read, exp kept in registers, block rowsum, SMEM RMW. No global atomics.
__global__ __launch_bounds__(THREADS, 2) void k_main(const float* __restrict__ x,
                                                     const int* __restrict__ tgt) {
    __shared__ float acc[CLASSES];   // class c lives at (c&3)*2500 + (c>>2)
    __shared__ float wred[16];
    __shared__ float s_inv;
    const int tid = threadIdx.x;

    for (int j = tid; j < CLASSES; j += THREADS) acc[j] = 0.0f;

    // label histogram side-job (blocks 0..7, 1024 targets each); dtype-robust:
    // detect int64-LE (odd int32 words zero for values < 2^32) vs int32.
    if (blockIdx.x < 8) {
        bool is64 = true;
        #pragma unroll
        for (int j = 1; j < 16; j += 2) is64 = is64 && (tgt[j] == 0);
        #pragma unroll
        for (int k = 0; k < 2; k++) {
            int i = blockIdx.x * 1024 + k * THREADS + tid;
            int t = is64 ? tgt[2 * i] : tgt[i];
            if (t >= 0 && t < CLASSES) atomicAdd(&g_counts[t], 1.0f);
        }
    }

    for (int row = blockIdx.x; row < BATCH; row += GRID) {
        const float4* __restrict__ rp =
            reinterpret_cast<const float4*>(x) + (size_t)row * C4;

        float e[5][4];
        float s = 0.0f;
        #pragma unroll
        for (int k = 0; k < 5; k++) {
            int i = tid + k * THREADS;
            if (i < C4) {
                float4 v = rp[i];
                e[k][0] = __expf(v.x); e[k][1] = __expf(v.y);
                e[k][2] = __expf(v.z); e[k][3] = __expf(v.w);
                s += (e[k][0] + e[k][1]) + (e[k][2] + e[k][3]);
            }
        }

        // block rowsum: warp shfl -> 16 partials -> warp0 -> s_inv
        #pragma unroll
        for (int o = 16; o; o >>= 1) s += __shfl_down_sync(0xffffffffu, s, o);
        if ((tid & 31) == 0) wred[tid >> 5] = s;
        __syncthreads();
        if (tid < 16) {
            float t = wred[tid];
            t += __shfl_down_sync(0xffffu, t, 8);
            t += __shfl_down_sync(0xffffu, t, 4);
            t += __shfl_down_sync(0xffffu, t, 2);
            t += __shfl_down_sync(0xffffu, t, 1);
            if (tid == 0) s_inv = 1.0f / t;
        }
        __syncthreads();
        const float inv = s_inv;

        // accumulate into SMEM (bank-conflict-free: stride-1 in i per j-plane)
        #pragma unroll
        for (int k = 0; k < 5; k++) {
            int i = tid + k * THREADS;
            if (i < C4) {
                acc[0 * C4 + i] += e[k][0] * inv;
                acc[1 * C4 + i] += e[k][1] * inv;
                acc[2 * C4 + i] += e[k][2] * inv;
                acc[3 * C4 + i] += e[k][3] * inv;
            }
        }
        // no barrier needed here: next row's wred/s_inv writes are fenced by
        // the two barriers above before any thread can observe them stale
    }

    __syncthreads();
    float* __restrict__ dst = g_part[blockIdx.x];
    for (int c = tid; c < CLASSES; c += THREADS)       // coalesced global stores
        dst[c] = acc[(c & 3) * C4 + (c >> 2)];
}

// ---------------------------------------------------------------- final reduce
__global__ __launch_bounds__(256) void k_final(float* __restrict__ out) {
    const float invB = 1.0f / (float)BATCH;
    float s = 0.0f;
    for (int c = blockIdx.x * 256 + threadIdx.x; c < CLASSES; c += gridDim.x * 256) {
        float v = 0.0f;
        #pragma unroll 4
        for (int p = 0; p < GRID; p++) v += g_part[p][c];   // coalesced across threads
        s += fabsf((v - g_counts[c]) * invB);
    }
    __shared__ float sm[8];
    #pragma unroll
    for (int o = 16; o; o >>= 1) s += __shfl_down_sync(0xffffffffu, s, o);
    if ((threadIdx.x & 31) == 0) sm[threadIdx.x >> 5] = s;
    __syncthreads();
    if (threadIdx.x < 8) {
        float t = sm[threadIdx.x];
        #pragma unroll
        for (int o = 4; o; o >>= 1) t += __shfl_down_sync(0xffu, t, o);
        if (threadIdx.x == 0) atomicAdd(out, t / (float)CLASSES);
    }
}

// ---------------------------------------------------------------- launch
extern "C" void kernel_launch(void* const* d_in, const int* in_sizes, int n_in,
                              void* d_out, int out_size) {
    const float* x   = (const float*)d_in[0];   // [8192, 10000] fp32
    const int*   tgt = (const int*)d_in[1];     // [8192] int32 or int64 (detected)
    float*       out = (float*)d_out;

    k_zero<<<(CLASSES + 255) / 256, 256>>>(out);
    k_main<<<GRID, THREADS>>>(x, tgt);
    k_final<<<40, 256>>>(out);
}

// round 6
// speedup vs baseline: 1.0407x; 1.0407x over previous
#include <cuda_runtime.h>

#define BATCH   8192
#define CLASSES 10000
#define C4      2500          // float4 per row
#define THREADS 256
#define KCHUNK  10            // float4 per thread per row (256*10 >= 2500)
#define GRID    304           // 2 persistent CTAs per SM

__device__ float g_part[GRID][CLASSES];   // per-CTA partials (fully overwritten)
__device__ float g_counts[CLASSES];

// ---------------------------------------------------------------- zero counts + out
__global__ void k_zero(float* __restrict__ out) {
    int i = blockIdx.x * blockDim.x + threadIdx.x;
    if (i < CLASSES) g_counts[i] = 0.0f;
    if (i == 0) out[0] = 0.0f;
}

// ---------------------------------------------------------------- persistent main
// Thread t of a CTA owns classes {4i..4i+3 : i = t + 256k, k<10} for EVERY row
// the CTA processes. exp values and per-class accumulators both live in
// registers; the only SMEM use is the 8-word row-sum reduction. No atomics.
__global__ __launch_bounds__(THREADS, 2) void k_main(const float* __restrict__ x,
                                                     const int* __restrict__ tgt) {
    __shared__ float wred[8];
    __shared__ float s_inv;
    const int tid = threadIdx.x;

    // label histogram side-job (blocks 0..31, 256 targets each); dtype-robust:
    // detect int64-LE (odd int32 words zero for values < 2^32) vs int32.
    if (blockIdx.x < 32) {
        bool is64 = true;
        #pragma unroll
        for (int j = 1; j < 16; j += 2) is64 = is64 && (tgt[j] == 0);
        int i = blockIdx.x * 256 + tid;
        int t = is64 ? tgt[2 * i] : tgt[i];
        if (t >= 0 && t < CLASSES) atomicAdd(&g_counts[t], 1.0f);
    }

    float acc[KCHUNK][4];
    #pragma unroll
    for (int k = 0; k < KCHUNK; k++)
        acc[k][0] = acc[k][1] = acc[k][2] = acc[k][3] = 0.0f;

    for (int row = blockIdx.x; row < BATCH; row += GRID) {
        const float4* __restrict__ rp =
            reinterpret_cast<const float4*>(x) + (size_t)row * C4;

        float e[KCHUNK][4];
        float s = 0.0f;
        #pragma unroll
        for (int k = 0; k < KCHUNK; k++) {
            int i = tid + k * THREADS;
            if (i < C4) {
                float4 v = rp[i];
                e[k][0] = __expf(v.x); e[k][1] = __expf(v.y);
                e[k][2] = __expf(v.z); e[k][3] = __expf(v.w);
                s += (e[k][0] + e[k][1]) + (e[k][2] + e[k][3]);
            }
        }

        // block rowsum: warp shfl -> 8 warp partials -> lane fanout
        #pragma unroll
        for (int o = 16; o; o >>= 1) s += __shfl_down_sync(0xffffffffu, s, o);
        if ((tid & 31) == 0) wred[tid >> 5] = s;
        __syncthreads();
        if (tid < 8) {
            float t = wred[tid];
            t += __shfl_down_sync(0xffu, t, 4);
            t += __shfl_down_sync(0xffu, t, 2);
            t += __shfl_down_sync(0xffu, t, 1);
            if (tid == 0) s_inv = 1.0f / t;
        }
        __syncthreads();
        const float inv = s_inv;

        // register accumulation — no shared-memory port traffic, no atomics
        #pragma unroll
        for (int k = 0; k < KCHUNK; k++) {
            int i = tid + k * THREADS;
            if (i < C4) {
                acc[k][0] += e[k][0] * inv;
                acc[k][1] += e[k][1] * inv;
                acc[k][2] += e[k][2] * inv;
                acc[k][3] += e[k][3] * inv;
            }
        }
        __syncthreads();   // protect wred/s_inv reuse next iteration
    }

    // flush per-CTA partials: coalesced float4 stores
    float4* __restrict__ dst = reinterpret_cast<float4*>(g_part[blockIdx.x]);
    #pragma unroll
    for (int k = 0; k < KCHUNK; k++) {
        int i = tid + k * THREADS;
        if (i < C4)
            dst[i] = make_float4(acc[k][0], acc[k][1], acc[k][2], acc[k][3]);
    }
}

// ---------------------------------------------------------------- final reduce
__global__ __launch_bounds__(256) void k_final(float* __restrict__ out) {
    const float invB = 1.0f / (float)BATCH;
    float s = 0.0f;
    for (int c = blockIdx.x * 256 + threadIdx.x; c < CLASSES; c += gridDim.x * 256) {
        float v = 0.0f;
        #pragma unroll 4
        for (int p = 0; p < GRID; p++) v += g_part[p][c];   // coalesced across threads
        s += fabsf((v - g_counts[c]) * invB);
    }
    __shared__ float sm[8];
    #pragma unroll
    for (int o = 16; o; o >>= 1) s += __shfl_down_sync(0xffffffffu, s, o);
    if ((threadIdx.x & 31) == 0) sm[threadIdx.x >> 5] = s;
    __syncthreads();
    if (threadIdx.x < 8) {
        float t = sm[threadIdx.x];
        #pragma unroll
        for (int o = 4; o; o >>= 1) t += __shfl_down_sync(0xffu, t, o);
        if (threadIdx.x == 0) atomicAdd(out, t / (float)CLASSES);
    }
}

// ---------------------------------------------------------------- launch
extern "C" void kernel_launch(void* const* d_in, const int* in_sizes, int n_in,
                              void* d_out, int out_size) {
    const float* x   = (const float*)d_in[0];   // [8192, 10000] fp32
    const int*   tgt = (const int*)d_in[1];     // [8192] int32 or int64 (detected)
    float*       out = (float*)d_out;

    k_zero<<<(CLASSES + 255) / 256, 256>>>(out);
    k_main<<<GRID, THREADS>>>(x, tgt);
    k_final<<<40, 256>>>(out);
}